// round 2
// baseline (speedup 1.0000x reference)
#include <cuda_runtime.h>
#include <cuda_bf16.h>
#include <math.h>

#define NN 50000
#define EE 800000
#define ETOT (EE + NN)
#define NEG_SLOPE 0.2f
#define EPS_DEN 1e-16f

// ---------------- scratch (static __device__, no allocs) ----------------
__device__ float g_h1[NN * 128];      // layer1 projected features [N,4,32]
__device__ float g_out1[NN * 128];    // layer1 aggregated output
__device__ float g_asrc1[NN * 4];
__device__ float g_adst1[NN * 4];
__device__ float g_m1[NN * 4];
__device__ float g_d1[NN * 4];
__device__ float g_e1[ETOT * 4];      // per-edge scores, then exp values

__device__ float g_h2[NN * 2];
__device__ float g_asrc2[NN];
__device__ float g_adst2[NN];
__device__ float g_m2[NN];
__device__ float g_d2[NN];
__device__ float g_out2[NN * 2];
__device__ float g_e2[ETOT];

// ---------------- helpers ----------------
__device__ __forceinline__ void atomicMaxFloat(float* addr, float val) {
    // monotone-mapping trick: int-max for >=0, uint-min for <0. Mixed ops converge to max.
    if (val >= 0.0f)
        atomicMax((int*)addr, __float_as_int(val));
    else
        atomicMin((unsigned int*)addr, __float_as_uint(val));
}

__device__ __forceinline__ void red_add_v4(float* p, float x, float y, float z, float w) {
    asm volatile("red.global.add.v4.f32 [%0], {%1, %2, %3, %4};"
                 :: "l"(__cvta_generic_to_global(p)), "f"(x), "f"(y), "f"(z), "f"(w)
                 : "memory");
}

__device__ __forceinline__ void red_add_v2(float* p, float x, float y) {
    asm volatile("red.global.add.v2.f32 [%0], {%1, %2};"
                 :: "l"(__cvta_generic_to_global(p)), "f"(x), "f"(y)
                 : "memory");
}

// edge_index is int32 on device (JAX default x64-disabled demotes int64->int32).
__device__ __forceinline__ void edge_sd(const int* __restrict__ ei, int e, int& s, int& d) {
    if (e < EE) {
        s = ei[e];
        d = ei[EE + e];
    } else {
        s = d = e - EE;   // self loop
    }
}

// ---------------- kernels ----------------

// zero / -inf init of all accumulators
__global__ void k_init() {
    int t = blockIdx.x * blockDim.x + threadIdx.x;
    if (t < NN * 128) g_out1[t] = 0.0f;
    if (t < NN * 4) { g_m1[t] = -INFINITY; g_d1[t] = 0.0f; }
    if (t < NN * 2) g_out2[t] = 0.0f;
    if (t < NN)     { g_m2[t] = -INFINITY; g_d2[t] = 0.0f; }
}

// h1 = x @ W1  (+ per-node attention scalars). 128 threads = one output column each;
// W column register-cached, x row staged through smem, 64 nodes per block.
#define GEMM1_NPB 64
__global__ __launch_bounds__(128) void k_gemm1(const float* __restrict__ x,
                                               const float* __restrict__ W1,
                                               const float* __restrict__ att_s,
                                               const float* __restrict__ att_d) {
    __shared__ float xs[128];
    const int j = threadIdx.x;
    const int lane = j & 31;
    const int head = j >> 5;

    float w[128];
#pragma unroll
    for (int k = 0; k < 128; k++) w[k] = W1[k * 128 + j];
    const float asj = att_s[j];
    const float adj = att_d[j];

    const int n0 = blockIdx.x * GEMM1_NPB;
#pragma unroll 1
    for (int nn = 0; nn < GEMM1_NPB; nn++) {
        const int n = n0 + nn;
        __syncthreads();
        if (n < NN) xs[j] = x[n * 128 + j];
        __syncthreads();
        if (n >= NN) continue;
        float acc = 0.0f;
#pragma unroll
        for (int k = 0; k < 128; k++) acc = fmaf(xs[k], w[k], acc);
        g_h1[n * 128 + j] = acc;
        float ps = acc * asj;
        float pd = acc * adj;
#pragma unroll
        for (int off = 16; off > 0; off >>= 1) {
            ps += __shfl_down_sync(0xffffffffu, ps, off);
            pd += __shfl_down_sync(0xffffffffu, pd, off);
        }
        if (lane == 0) {
            g_asrc1[n * 4 + head] = ps;
            g_adst1[n * 4 + head] = pd;
        }
    }
}

// pass 1: edge scores + segment max (per edge, per head)
__global__ void k_edge1_max(const int* __restrict__ ei) {
    int t = blockIdx.x * blockDim.x + threadIdx.x;
    if (t >= ETOT * 4) return;
    int e = t >> 2, h = t & 3;
    int s, d;
    edge_sd(ei, e, s, d);
    float v = g_asrc1[s * 4 + h] + g_adst1[d * 4 + h];
    v = (v > 0.0f) ? v : NEG_SLOPE * v;
    g_e1[t] = v;
    atomicMaxFloat(&g_m1[d * 4 + h], v);
}

// pass 2: exp(e - max) + segment sum
__global__ void k_edge1_exp(const int* __restrict__ ei) {
    int t = blockIdx.x * blockDim.x + threadIdx.x;
    if (t >= ETOT * 4) return;
    int e = t >> 2, h = t & 3;
    int s, d;
    edge_sd(ei, e, s, d);
    (void)s;
    float ex = expf(g_e1[t] - g_m1[d * 4 + h]);
    g_e1[t] = ex;
    atomicAdd(&g_d1[d * 4 + h], ex);
}

// pass 3: out1[dst] += alpha * h1[src]  — one warp per edge, vector RED
__global__ void k_edge1_aggr(const int* __restrict__ ei) {
    int gt = blockIdx.x * blockDim.x + threadIdx.x;
    int e = gt >> 5;
    if (e >= ETOT) return;
    int lane = gt & 31;
    int s, d;
    edge_sd(ei, e, s, d);
    float a4 = 0.0f;
    if (lane < 4) a4 = g_e1[e * 4 + lane] / (g_d1[d * 4 + lane] + EPS_DEN);
    float alpha = __shfl_sync(0xffffffffu, a4, lane >> 3);   // head = (4*lane)/32
    float4 v = reinterpret_cast<const float4*>(g_h1)[s * 32 + lane];
    red_add_v4(&g_out1[d * 128 + 4 * lane], alpha * v.x, alpha * v.y, alpha * v.z, alpha * v.w);
}

// node pass: ELU(out1 + b1), project with W2 -> h2, attention scalars for layer 2
__global__ void k_node1(const float* __restrict__ b1,
                        const float* __restrict__ W2,
                        const float* __restrict__ att_s2,
                        const float* __restrict__ att_d2) {
    int gt = blockIdx.x * blockDim.x + threadIdx.x;
    int n = gt >> 5;
    if (n >= NN) return;
    int lane = gt & 31;
    float p0 = 0.0f, p1 = 0.0f;
#pragma unroll
    for (int i = 0; i < 4; i++) {
        int k = lane + 32 * i;
        float v = g_out1[n * 128 + k] + b1[k];
        float ev = (v > 0.0f) ? v : expm1f(v);   // ELU
        p0 = fmaf(ev, W2[k * 2 + 0], p0);
        p1 = fmaf(ev, W2[k * 2 + 1], p1);
    }
#pragma unroll
    for (int off = 16; off > 0; off >>= 1) {
        p0 += __shfl_down_sync(0xffffffffu, p0, off);
        p1 += __shfl_down_sync(0xffffffffu, p1, off);
    }
    if (lane == 0) {
        g_h2[n * 2 + 0] = p0;
        g_h2[n * 2 + 1] = p1;
        g_asrc2[n] = p0 * att_s2[0] + p1 * att_s2[1];
        g_adst2[n] = p0 * att_d2[0] + p1 * att_d2[1];
    }
}

__global__ void k_edge2_max(const int* __restrict__ ei) {
    int e = blockIdx.x * blockDim.x + threadIdx.x;
    if (e >= ETOT) return;
    int s, d;
    edge_sd(ei, e, s, d);
    float v = g_asrc2[s] + g_adst2[d];
    v = (v > 0.0f) ? v : NEG_SLOPE * v;
    g_e2[e] = v;
    atomicMaxFloat(&g_m2[d], v);
}

__global__ void k_edge2_exp(const int* __restrict__ ei) {
    int e = blockIdx.x * blockDim.x + threadIdx.x;
    if (e >= ETOT) return;
    int s, d;
    edge_sd(ei, e, s, d);
    (void)s;
    float ex = expf(g_e2[e] - g_m2[d]);
    g_e2[e] = ex;
    atomicAdd(&g_d2[d], ex);
}

__global__ void k_edge2_aggr(const int* __restrict__ ei) {
    int e = blockIdx.x * blockDim.x + threadIdx.x;
    if (e >= ETOT) return;
    int s, d;
    edge_sd(ei, e, s, d);
    float alpha = g_e2[e] / (g_d2[d] + EPS_DEN);
    red_add_v2(&g_out2[d * 2], alpha * g_h2[s * 2 + 0], alpha * g_h2[s * 2 + 1]);
}

__global__ void k_final(const float* __restrict__ b2, float* __restrict__ out) {
    int n = blockIdx.x * blockDim.x + threadIdx.x;
    if (n >= NN) return;
    float a = g_out2[n * 2 + 0] + b2[0];
    float b = g_out2[n * 2 + 1] + b2[1];
    float m = fmaxf(a, b);
    float l = m + logf(expf(a - m) + expf(b - m));
    out[n * 2 + 0] = a - l;
    out[n * 2 + 1] = b - l;
}

// ---------------- launch ----------------
extern "C" void kernel_launch(void* const* d_in, const int* in_sizes, int n_in,
                              void* d_out, int out_size) {
    const float* x    = (const float*)d_in[0];
    const int*   ei   = (const int*)d_in[1];
    const float* W1   = (const float*)d_in[2];
    const float* as1  = (const float*)d_in[3];
    const float* ad1  = (const float*)d_in[4];
    const float* b1   = (const float*)d_in[5];
    const float* W2   = (const float*)d_in[6];
    const float* as2  = (const float*)d_in[7];
    const float* ad2  = (const float*)d_in[8];
    const float* b2   = (const float*)d_in[9];
    float* out = (float*)d_out;

    (void)in_sizes; (void)n_in; (void)out_size;

    {   // init accumulators
        int tot = NN * 128;
        k_init<<<(tot + 255) / 256, 256>>>();
    }
    k_gemm1<<<(NN + GEMM1_NPB - 1) / GEMM1_NPB, 128>>>(x, W1, as1, ad1);
    {
        int tot = ETOT * 4;
        k_edge1_max<<<(tot + 255) / 256, 256>>>(ei);
        k_edge1_exp<<<(tot + 255) / 256, 256>>>(ei);
    }
    {
        long long tot = (long long)ETOT * 32;
        k_edge1_aggr<<<(int)((tot + 255) / 256), 256>>>(ei);
    }
    {
        long long tot = (long long)NN * 32;
        k_node1<<<(int)((tot + 255) / 256), 256>>>(b1, W2, as2, ad2);
    }
    k_edge2_max<<<(ETOT + 255) / 256, 256>>>(ei);
    k_edge2_exp<<<(ETOT + 255) / 256, 256>>>(ei);
    k_edge2_aggr<<<(ETOT + 255) / 256, 256>>>(ei);
    k_final<<<(NN + 255) / 256, 256>>>(b2, out);
}

// round 3
// speedup vs baseline: 1.1729x; 1.1729x over previous
#include <cuda_runtime.h>
#include <cuda_bf16.h>
#include <math.h>

#define NN 50000
#define EE 800000
#define ETOT (EE + NN)
#define NEG_SLOPE 0.2f
#define EPS_DEN 1e-16f

// ---------------- scratch (static __device__, no allocs) ----------------
__device__ float g_h1[NN * 128];      // layer1 projected features [N,4,32]
__device__ float g_out1[NN * 128];    // layer1 aggregated (unnormalized)
__device__ float g_asrc1[NN * 4];
__device__ float g_adst1[NN * 4];
__device__ float g_d1[NN * 4];        // softmax denominators
__device__ float g_e1[ETOT * 4];      // per-edge exp values

__device__ float g_h2[NN * 2];
__device__ float g_asrc2[NN];
__device__ float g_adst2[NN];
__device__ float g_d2[NN];
__device__ float g_out2[NN * 2];      // unnormalized
__device__ float g_e2[ETOT];

// ---------------- helpers ----------------
__device__ __forceinline__ void red_add_v4(float* p, float x, float y, float z, float w) {
    asm volatile("red.global.add.v4.f32 [%0], {%1, %2, %3, %4};"
                 :: "l"(__cvta_generic_to_global(p)), "f"(x), "f"(y), "f"(z), "f"(w)
                 : "memory");
}

__device__ __forceinline__ void red_add_v2(float* p, float x, float y) {
    asm volatile("red.global.add.v2.f32 [%0], {%1, %2};"
                 :: "l"(__cvta_generic_to_global(p)), "f"(x), "f"(y)
                 : "memory");
}

// edge_index is int32 on device (JAX x64-disabled demotes int64->int32)
__device__ __forceinline__ void edge_sd(const int* __restrict__ ei, int e, int& s, int& d) {
    if (e < EE) {
        s = ei[e];
        d = ei[EE + e];
    } else {
        s = d = e - EE;   // self loop
    }
}

// ---------------- kernels ----------------

// zero accumulators (out1, d1, out2, d2)
__global__ void k_init() {
    int t = blockIdx.x * blockDim.x + threadIdx.x;
    if (t < NN * 128) g_out1[t] = 0.0f;
    if (t < NN * 4) g_d1[t] = 0.0f;
    if (t < NN * 2) g_out2[t] = 0.0f;
    if (t < NN)     g_d2[t] = 0.0f;
}

// h1 = x @ W1 (+ attention scalars). 128 threads = 1 output column each,
// W column register-cached, x row staged through smem (float4), 4-way ILP accums.
#define GEMM1_NPB 64
__global__ __launch_bounds__(128) void k_gemm1(const float* __restrict__ x,
                                               const float* __restrict__ W1,
                                               const float* __restrict__ att_s,
                                               const float* __restrict__ att_d) {
    __shared__ float4 xs[32];
    const int j = threadIdx.x;
    const int lane = j & 31;
    const int head = j >> 5;

    float w[128];
#pragma unroll
    for (int k = 0; k < 128; k++) w[k] = W1[k * 128 + j];
    const float asj = att_s[j];
    const float adj = att_d[j];

    const int n0 = blockIdx.x * GEMM1_NPB;
#pragma unroll 1
    for (int nn = 0; nn < GEMM1_NPB; nn++) {
        const int n = n0 + nn;
        __syncthreads();
        if (j < 32 && n < NN) xs[j] = reinterpret_cast<const float4*>(x)[n * 32 + j];
        __syncthreads();
        if (n >= NN) continue;
        float a0 = 0.0f, a1 = 0.0f, a2 = 0.0f, a3 = 0.0f;
#pragma unroll
        for (int k = 0; k < 32; k++) {
            float4 v = xs[k];
            a0 = fmaf(v.x, w[4 * k + 0], a0);
            a1 = fmaf(v.y, w[4 * k + 1], a1);
            a2 = fmaf(v.z, w[4 * k + 2], a2);
            a3 = fmaf(v.w, w[4 * k + 3], a3);
        }
        float acc = (a0 + a1) + (a2 + a3);
        g_h1[n * 128 + j] = acc;
        float ps = acc * asj;
        float pd = acc * adj;
#pragma unroll
        for (int off = 16; off > 0; off >>= 1) {
            ps += __shfl_down_sync(0xffffffffu, ps, off);
            pd += __shfl_down_sync(0xffffffffu, pd, off);
        }
        if (lane == 0) {
            g_asrc1[n * 4 + head] = ps;
            g_adst1[n * 4 + head] = pd;
        }
    }
}

// fused: score -> leakyReLU -> exp -> store + segment-sum. Thread per edge, all 4 heads.
__global__ void k_edge1_fused(const int* __restrict__ ei) {
    int e = blockIdx.x * blockDim.x + threadIdx.x;
    if (e >= ETOT) return;
    int s, d;
    edge_sd(ei, e, s, d);
    float4 as = reinterpret_cast<const float4*>(g_asrc1)[s];
    float4 ad = reinterpret_cast<const float4*>(g_adst1)[d];
    float v0 = as.x + ad.x, v1 = as.y + ad.y, v2 = as.z + ad.z, v3 = as.w + ad.w;
    v0 = (v0 > 0.0f) ? v0 : NEG_SLOPE * v0;
    v1 = (v1 > 0.0f) ? v1 : NEG_SLOPE * v1;
    v2 = (v2 > 0.0f) ? v2 : NEG_SLOPE * v2;
    v3 = (v3 > 0.0f) ? v3 : NEG_SLOPE * v3;
    float e0 = expf(v0), e1 = expf(v1), e2 = expf(v2), e3 = expf(v3);
    reinterpret_cast<float4*>(g_e1)[e] = make_float4(e0, e1, e2, e3);
    red_add_v4(&g_d1[d * 4], e0, e1, e2, e3);
}

// aggregation: out1[dst] += ex * h1[src] — one warp per edge, vector RED
__global__ void k_edge1_aggr(const int* __restrict__ ei) {
    int gt = blockIdx.x * blockDim.x + threadIdx.x;
    int e = gt >> 5;
    if (e >= ETOT) return;
    int lane = gt & 31;
    int s, d;
    edge_sd(ei, e, s, d);
    float a4 = 0.0f;
    if (lane < 4) a4 = g_e1[e * 4 + lane];
    float ex = __shfl_sync(0xffffffffu, a4, lane >> 3);   // head = lane/8
    float4 v = reinterpret_cast<const float4*>(g_h1)[s * 32 + lane];
    red_add_v4(&g_out1[d * 128 + 4 * lane], ex * v.x, ex * v.y, ex * v.z, ex * v.w);
}

// node pass: normalize, +b1, ELU, project W2 -> h2 + layer-2 attention scalars.
// one warp per node.
__global__ void k_node1(const float* __restrict__ b1,
                        const float* __restrict__ W2,
                        const float* __restrict__ att_s2,
                        const float* __restrict__ att_d2) {
    int gt = blockIdx.x * blockDim.x + threadIdx.x;
    int n = gt >> 5;
    if (n >= NN) return;
    int lane = gt & 31;
    float4 dd = reinterpret_cast<const float4*>(g_d1)[n];   // broadcast
    float r0 = 1.0f / (dd.x + EPS_DEN);
    float r1 = 1.0f / (dd.y + EPS_DEN);
    float r2 = 1.0f / (dd.z + EPS_DEN);
    float r3 = 1.0f / (dd.w + EPS_DEN);
    float rc[4] = {r0, r1, r2, r3};
    float p0 = 0.0f, p1 = 0.0f;
#pragma unroll
    for (int i = 0; i < 4; i++) {
        int k = lane + 32 * i;
        float v = g_out1[n * 128 + k] * rc[i] + b1[k];
        float ev = (v > 0.0f) ? v : expm1f(v);   // ELU
        p0 = fmaf(ev, W2[k * 2 + 0], p0);
        p1 = fmaf(ev, W2[k * 2 + 1], p1);
    }
#pragma unroll
    for (int off = 16; off > 0; off >>= 1) {
        p0 += __shfl_down_sync(0xffffffffu, p0, off);
        p1 += __shfl_down_sync(0xffffffffu, p1, off);
    }
    if (lane == 0) {
        g_h2[n * 2 + 0] = p0;
        g_h2[n * 2 + 1] = p1;
        g_asrc2[n] = p0 * att_s2[0] + p1 * att_s2[1];
        g_adst2[n] = p0 * att_d2[0] + p1 * att_d2[1];
    }
}

// fused layer-2 edge pass: score -> leakyReLU -> exp -> store + sum
__global__ void k_edge2_fused(const int* __restrict__ ei) {
    int e = blockIdx.x * blockDim.x + threadIdx.x;
    if (e >= ETOT) return;
    int s, d;
    edge_sd(ei, e, s, d);
    float v = g_asrc2[s] + g_adst2[d];
    v = (v > 0.0f) ? v : NEG_SLOPE * v;
    float ex = expf(v);
    g_e2[e] = ex;
    atomicAdd(&g_d2[d], ex);
}

__global__ void k_edge2_aggr(const int* __restrict__ ei) {
    int e = blockIdx.x * blockDim.x + threadIdx.x;
    if (e >= ETOT) return;
    int s, d;
    edge_sd(ei, e, s, d);
    float ex = g_e2[e];
    red_add_v2(&g_out2[d * 2], ex * g_h2[s * 2 + 0], ex * g_h2[s * 2 + 1]);
}

__global__ void k_final(const float* __restrict__ b2, float* __restrict__ out) {
    int n = blockIdx.x * blockDim.x + threadIdx.x;
    if (n >= NN) return;
    float r = 1.0f / (g_d2[n] + EPS_DEN);
    float a = g_out2[n * 2 + 0] * r + b2[0];
    float b = g_out2[n * 2 + 1] * r + b2[1];
    float m = fmaxf(a, b);
    float l = m + logf(expf(a - m) + expf(b - m));
    out[n * 2 + 0] = a - l;
    out[n * 2 + 1] = b - l;
}

// ---------------- launch ----------------
extern "C" void kernel_launch(void* const* d_in, const int* in_sizes, int n_in,
                              void* d_out, int out_size) {
    const float* x    = (const float*)d_in[0];
    const int*   ei   = (const int*)d_in[1];
    const float* W1   = (const float*)d_in[2];
    const float* as1  = (const float*)d_in[3];
    const float* ad1  = (const float*)d_in[4];
    const float* b1   = (const float*)d_in[5];
    const float* W2   = (const float*)d_in[6];
    const float* as2  = (const float*)d_in[7];
    const float* ad2  = (const float*)d_in[8];
    const float* b2   = (const float*)d_in[9];
    float* out = (float*)d_out;

    (void)in_sizes; (void)n_in; (void)out_size;

    k_init<<<(NN * 128 + 255) / 256, 256>>>();
    k_gemm1<<<(NN + GEMM1_NPB - 1) / GEMM1_NPB, 128>>>(x, W1, as1, ad1);
    k_edge1_fused<<<(ETOT + 255) / 256, 256>>>(ei);
    {
        long long tot = (long long)ETOT * 32;
        k_edge1_aggr<<<(int)((tot + 255) / 256), 256>>>(ei);
    }
    {
        long long tot = (long long)NN * 32;
        k_node1<<<(int)((tot + 255) / 256), 256>>>(b1, W2, as2, ad2);
    }
    k_edge2_fused<<<(ETOT + 255) / 256, 256>>>(ei);
    k_edge2_aggr<<<(ETOT + 255) / 256, 256>>>(ei);
    k_final<<<(NN + 255) / 256, 256>>>(b2, out);
}

// round 4
// speedup vs baseline: 1.5039x; 1.2821x over previous
#include <cuda_runtime.h>
#include <cuda_bf16.h>
#include <math.h>

#define NN 50000
#define EE 800000
#define ETOT (EE + NN)
#define NEG_SLOPE 0.2f
#define EPS_DEN 1e-16f

#define SCAN_T 256
#define SCAN_ITEMS 4                       // 1024 elements per block
#define SCAN_B ((NN + 1023) / 1024)        // 49 blocks

// ---------------- scratch (static __device__, no allocs) ----------------
__device__ float g_h1[NN * 128];      // layer1 projected features [N,4,32]
__device__ float g_asrc1[NN * 4];
__device__ float g_adst1[NN * 4];
__device__ float g_h2[NN * 2];
__device__ float g_asrc2[NN];
__device__ float g_adst2[NN];

__device__ int g_deg[NN];
__device__ int g_scan[NN];
__device__ int g_bsum[64];
__device__ int g_boff[64];
__device__ int g_rowptr[NN + 1];
__device__ int g_cursor[NN];
__device__ int g_csrc[ETOT];          // CSR: src node per dst-grouped slot

// ---------------- CSR build ----------------
__global__ void k_initdeg() {
    int n = blockIdx.x * blockDim.x + threadIdx.x;
    if (n < NN) g_deg[n] = 1;          // self loop
}

// edge_index is int32 on device (JAX x64-disabled demotes int64->int32)
__global__ void k_count(const int* __restrict__ ei) {
    int e = blockIdx.x * blockDim.x + threadIdx.x;
    if (e < EE) atomicAdd(&g_deg[ei[EE + e]], 1);
}

__global__ __launch_bounds__(SCAN_T) void k_scanA() {
    __shared__ int sdata[SCAN_T];
    int blk = blockIdx.x, t = threadIdx.x;
    int base = blk * (SCAN_T * SCAN_ITEMS) + t * SCAN_ITEMS;
    int v[SCAN_ITEMS];
    int sum = 0;
#pragma unroll
    for (int i = 0; i < SCAN_ITEMS; i++) {
        int idx = base + i;
        v[i] = (idx < NN) ? g_deg[idx] : 0;
        sum += v[i];
    }
    sdata[t] = sum;
    __syncthreads();
    for (int off = 1; off < SCAN_T; off <<= 1) {
        int x = (t >= off) ? sdata[t - off] : 0;
        __syncthreads();
        sdata[t] += x;
        __syncthreads();
    }
    int excl = sdata[t] - sum;
    if (t == SCAN_T - 1) g_bsum[blk] = sdata[t];
    int run = excl;
#pragma unroll
    for (int i = 0; i < SCAN_ITEMS; i++) {
        int idx = base + i;
        if (idx < NN) g_scan[idx] = run;
        run += v[i];
    }
}

__global__ __launch_bounds__(64) void k_scanB() {
    __shared__ int sdata[64];
    int t = threadIdx.x;
    int val = (t < SCAN_B) ? g_bsum[t] : 0;
    sdata[t] = val;
    __syncthreads();
    for (int off = 1; off < 64; off <<= 1) {
        int x = (t >= off) ? sdata[t - off] : 0;
        __syncthreads();
        sdata[t] += x;
        __syncthreads();
    }
    if (t < SCAN_B) g_boff[t] = sdata[t] - val;   // exclusive
}

__global__ void k_scanC() {
    int i = blockIdx.x * blockDim.x + threadIdx.x;
    if (i < NN) {
        int r = g_scan[i] + g_boff[i / (SCAN_T * SCAN_ITEMS)];
        g_rowptr[i] = r;
        g_cursor[i] = r;
    }
    if (i == 0) g_rowptr[NN] = ETOT;
}

__global__ void k_scatter(const int* __restrict__ ei) {
    int e = blockIdx.x * blockDim.x + threadIdx.x;
    if (e >= ETOT) return;
    int s, d;
    if (e < EE) { s = ei[e]; d = ei[EE + e]; }
    else        { s = d = e - EE; }
    int pos = atomicAdd(&g_cursor[d], 1);
    g_csrc[pos] = s;
}

// ---------------- GEMM1: h1 = x @ W1 + attention scalars ----------------
#define GEMM1_NPB 64
__global__ __launch_bounds__(128) void k_gemm1(const float* __restrict__ x,
                                               const float* __restrict__ W1,
                                               const float* __restrict__ att_s,
                                               const float* __restrict__ att_d) {
    __shared__ float4 xs[32];
    const int j = threadIdx.x;
    const int lane = j & 31;
    const int head = j >> 5;

    float w[128];
#pragma unroll
    for (int k = 0; k < 128; k++) w[k] = W1[k * 128 + j];
    const float asj = att_s[j];
    const float adj = att_d[j];

    const int n0 = blockIdx.x * GEMM1_NPB;
#pragma unroll 1
    for (int nn = 0; nn < GEMM1_NPB; nn++) {
        const int n = n0 + nn;
        __syncthreads();
        if (j < 32 && n < NN) xs[j] = reinterpret_cast<const float4*>(x)[n * 32 + j];
        __syncthreads();
        if (n >= NN) continue;
        float a0 = 0.0f, a1 = 0.0f, a2 = 0.0f, a3 = 0.0f;
#pragma unroll
        for (int k = 0; k < 32; k++) {
            float4 v = xs[k];
            a0 = fmaf(v.x, w[4 * k + 0], a0);
            a1 = fmaf(v.y, w[4 * k + 1], a1);
            a2 = fmaf(v.z, w[4 * k + 2], a2);
            a3 = fmaf(v.w, w[4 * k + 3], a3);
        }
        float acc = (a0 + a1) + (a2 + a3);
        g_h1[n * 128 + j] = acc;
        float ps = acc * asj;
        float pd = acc * adj;
#pragma unroll
        for (int off = 16; off > 0; off >>= 1) {
            ps += __shfl_down_sync(0xffffffffu, ps, off);
            pd += __shfl_down_sync(0xffffffffu, pd, off);
        }
        if (lane == 0) {
            g_asrc1[n * 4 + head] = ps;
            g_adst1[n * 4 + head] = pd;
        }
    }
}

// ---------------- fused layer 1: softmax + aggregate + ELU + W2 proj ----------------
// one warp per destination node
__global__ __launch_bounds__(256) void k_layer1(const float* __restrict__ b1,
                                                const float* __restrict__ W2,
                                                const float* __restrict__ att_s2,
                                                const float* __restrict__ att_d2) {
    int gt = blockIdx.x * blockDim.x + threadIdx.x;
    int n = gt >> 5;
    if (n >= NN) return;
    const int lane = gt & 31;
    const int head = lane >> 3;
    const unsigned FULL = 0xffffffffu;

    const int beg = g_rowptr[n];
    const int end = g_rowptr[n + 1];
    const float4 adn = reinterpret_cast<const float4*>(g_adst1)[n];

    float acc0 = 0.0f, acc1 = 0.0f, acc2 = 0.0f, acc3 = 0.0f;
    float dx = 0.0f, dy = 0.0f, dz = 0.0f, dw = 0.0f;   // per-lane denom partials

    for (int c = beg; c < end; c += 32) {
        const int idx = c + lane;
        const int cnt = min(32, end - c);
        int s_mine = 0;
        float ex0 = 0.0f, ex1 = 0.0f, ex2 = 0.0f, ex3 = 0.0f;
        if (idx < end) {
            s_mine = g_csrc[idx];
            float4 as_ = reinterpret_cast<const float4*>(g_asrc1)[s_mine];
            float v0 = as_.x + adn.x, v1 = as_.y + adn.y;
            float v2 = as_.z + adn.z, v3 = as_.w + adn.w;
            v0 = (v0 > 0.0f) ? v0 : NEG_SLOPE * v0;
            v1 = (v1 > 0.0f) ? v1 : NEG_SLOPE * v1;
            v2 = (v2 > 0.0f) ? v2 : NEG_SLOPE * v2;
            v3 = (v3 > 0.0f) ? v3 : NEG_SLOPE * v3;
            ex0 = expf(v0); ex1 = expf(v1); ex2 = expf(v2); ex3 = expf(v3);
            dx += ex0; dy += ex1; dz += ex2; dw += ex3;
        }
        for (int j = 0; j < cnt; j++) {
            int s = __shfl_sync(FULL, s_mine, j);
            float e0 = __shfl_sync(FULL, ex0, j);
            float e1 = __shfl_sync(FULL, ex1, j);
            float e2 = __shfl_sync(FULL, ex2, j);
            float e3 = __shfl_sync(FULL, ex3, j);
            float ex = (head == 0) ? e0 : (head == 1) ? e1 : (head == 2) ? e2 : e3;
            float4 h = reinterpret_cast<const float4*>(g_h1)[s * 32 + lane];
            acc0 = fmaf(ex, h.x, acc0);
            acc1 = fmaf(ex, h.y, acc1);
            acc2 = fmaf(ex, h.z, acc2);
            acc3 = fmaf(ex, h.w, acc3);
        }
    }
    // full-warp reduce of the 4 denominators (result in all lanes)
#pragma unroll
    for (int off = 16; off > 0; off >>= 1) {
        dx += __shfl_xor_sync(FULL, dx, off);
        dy += __shfl_xor_sync(FULL, dy, off);
        dz += __shfl_xor_sync(FULL, dz, off);
        dw += __shfl_xor_sync(FULL, dw, off);
    }
    float denh = (head == 0) ? dx : (head == 1) ? dy : (head == 2) ? dz : dw;
    float r = 1.0f / (denh + EPS_DEN);

    // epilogue: normalize, +b1, ELU, project with W2
    float p0 = 0.0f, p1 = 0.0f;
    float av[4] = {acc0, acc1, acc2, acc3};
#pragma unroll
    for (int m = 0; m < 4; m++) {
        int k = 4 * lane + m;
        float v = av[m] * r + b1[k];
        float ev = (v > 0.0f) ? v : expm1f(v);   // ELU
        p0 = fmaf(ev, W2[k * 2 + 0], p0);
        p1 = fmaf(ev, W2[k * 2 + 1], p1);
    }
#pragma unroll
    for (int off = 16; off > 0; off >>= 1) {
        p0 += __shfl_down_sync(FULL, p0, off);
        p1 += __shfl_down_sync(FULL, p1, off);
    }
    if (lane == 0) {
        g_h2[n * 2 + 0] = p0;
        g_h2[n * 2 + 1] = p1;
        g_asrc2[n] = p0 * att_s2[0] + p1 * att_s2[1];
        g_adst2[n] = p0 * att_d2[0] + p1 * att_d2[1];
    }
}

// ---------------- fused layer 2: softmax + aggregate + log_softmax ----------------
// one warp per destination node, lanes stride edges
__global__ __launch_bounds__(256) void k_layer2(const float* __restrict__ b2,
                                                float* __restrict__ out) {
    int gt = blockIdx.x * blockDim.x + threadIdx.x;
    int n = gt >> 5;
    if (n >= NN) return;
    const int lane = gt & 31;
    const unsigned FULL = 0xffffffffu;

    const int beg = g_rowptr[n];
    const int end = g_rowptr[n + 1];
    const float adn = g_adst2[n];

    float den = 0.0f, o0 = 0.0f, o1 = 0.0f;
    for (int idx = beg + lane; idx < end; idx += 32) {
        int s = g_csrc[idx];
        float v = g_asrc2[s] + adn;
        v = (v > 0.0f) ? v : NEG_SLOPE * v;
        float ex = expf(v);
        float2 h = reinterpret_cast<const float2*>(g_h2)[s];
        den += ex;
        o0 = fmaf(ex, h.x, o0);
        o1 = fmaf(ex, h.y, o1);
    }
#pragma unroll
    for (int off = 16; off > 0; off >>= 1) {
        den += __shfl_down_sync(FULL, den, off);
        o0  += __shfl_down_sync(FULL, o0, off);
        o1  += __shfl_down_sync(FULL, o1, off);
    }
    if (lane == 0) {
        float r = 1.0f / (den + EPS_DEN);
        float a = o0 * r + b2[0];
        float b = o1 * r + b2[1];
        float m = fmaxf(a, b);
        float l = m + logf(expf(a - m) + expf(b - m));
        out[n * 2 + 0] = a - l;
        out[n * 2 + 1] = b - l;
    }
}

// ---------------- launch ----------------
extern "C" void kernel_launch(void* const* d_in, const int* in_sizes, int n_in,
                              void* d_out, int out_size) {
    const float* x    = (const float*)d_in[0];
    const int*   ei   = (const int*)d_in[1];
    const float* W1   = (const float*)d_in[2];
    const float* as1  = (const float*)d_in[3];
    const float* ad1  = (const float*)d_in[4];
    const float* b1   = (const float*)d_in[5];
    const float* W2   = (const float*)d_in[6];
    const float* as2  = (const float*)d_in[7];
    const float* ad2  = (const float*)d_in[8];
    const float* b2   = (const float*)d_in[9];
    float* out = (float*)d_out;

    (void)in_sizes; (void)n_in; (void)out_size;

    // CSR build (dst-grouped)
    k_initdeg<<<(NN + 255) / 256, 256>>>();
    k_count<<<(EE + 255) / 256, 256>>>(ei);
    k_scanA<<<SCAN_B, SCAN_T>>>();
    k_scanB<<<1, 64>>>();
    k_scanC<<<(NN + 255) / 256, 256>>>();
    k_scatter<<<(ETOT + 255) / 256, 256>>>(ei);

    // dense projection (runs while CSR chain is its own dependency stream in-order; fine)
    k_gemm1<<<(NN + GEMM1_NPB - 1) / GEMM1_NPB, 128>>>(x, W1, as1, ad1);

    {
        long long tot = (long long)NN * 32;
        k_layer1<<<(int)((tot + 255) / 256), 256>>>(b1, W2, as2, ad2);
        k_layer2<<<(int)((tot + 255) / 256), 256>>>(b2, out);
    }
}

// round 5
// speedup vs baseline: 1.8783x; 1.2490x over previous
#include <cuda_runtime.h>
#include <cuda_bf16.h>
#include <math.h>

#define NN 50000
#define EE 800000
#define ETOT (EE + NN)
#define NEG_SLOPE 0.2f
#define EPS_DEN 1e-16f

// ---------------- scratch (static __device__, no allocs) ----------------
__device__ float g_h1[NN * 128];      // layer1 projected features [N,4,32]
__device__ float g_asrc1[NN * 4];
__device__ float g_adst1[NN * 4];
__device__ float g_h2[NN * 2];
__device__ float g_asrc2[NN];
__device__ float g_adst2[NN];

__device__ int g_deg[NN];
__device__ int g_rowstart[NN];
__device__ int g_cursor[NN];
__device__ int g_total;
__device__ int g_csrc[ETOT];          // CSR: src node per dst-grouped slot

// ---------------- CSR build ----------------
__global__ void k_initdeg() {
    int n = blockIdx.x * blockDim.x + threadIdx.x;
    if (n < NN) g_deg[n] = 1;          // self loop
    if (n == 0) g_total = 0;
}

// edge_index is int32 on device (JAX x64-disabled demotes int64->int32)
__global__ void k_count(const int* __restrict__ ei) {
    int e = blockIdx.x * blockDim.x + threadIdx.x;
    if (e < EE) atomicAdd(&g_deg[ei[EE + e]], 1);
}

// row offsets via one global atomic — row ORDER is irrelevant, only per-node
// contiguity matters for the gather kernels.
__global__ void k_offsets() {
    int n = blockIdx.x * blockDim.x + threadIdx.x;
    if (n >= NN) return;
    int d = g_deg[n];
    int r = atomicAdd(&g_total, d);
    g_rowstart[n] = r;
    g_cursor[n] = r;
}

__global__ void k_scatter(const int* __restrict__ ei) {
    int e = blockIdx.x * blockDim.x + threadIdx.x;
    if (e >= ETOT) return;
    int s, d;
    if (e < EE) { s = ei[e]; d = ei[EE + e]; }
    else        { s = d = e - EE; }
    int pos = atomicAdd(&g_cursor[d], 1);
    g_csrc[pos] = s;
}

// ---------------- GEMM1: h1 = x @ W1 + attention scalars ----------------
#define GEMM1_NPB 64
__global__ __launch_bounds__(128) void k_gemm1(const float* __restrict__ x,
                                               const float* __restrict__ W1,
                                               const float* __restrict__ att_s,
                                               const float* __restrict__ att_d) {
    __shared__ float4 xs[32];
    const int j = threadIdx.x;
    const int lane = j & 31;
    const int head = j >> 5;

    float w[128];
#pragma unroll
    for (int k = 0; k < 128; k++) w[k] = W1[k * 128 + j];
    const float asj = att_s[j];
    const float adj = att_d[j];

    const int n0 = blockIdx.x * GEMM1_NPB;
#pragma unroll 1
    for (int nn = 0; nn < GEMM1_NPB; nn++) {
        const int n = n0 + nn;
        __syncthreads();
        if (j < 32 && n < NN) xs[j] = reinterpret_cast<const float4*>(x)[n * 32 + j];
        __syncthreads();
        if (n >= NN) continue;
        float a0 = 0.0f, a1 = 0.0f, a2 = 0.0f, a3 = 0.0f;
#pragma unroll
        for (int k = 0; k < 32; k++) {
            float4 v = xs[k];
            a0 = fmaf(v.x, w[4 * k + 0], a0);
            a1 = fmaf(v.y, w[4 * k + 1], a1);
            a2 = fmaf(v.z, w[4 * k + 2], a2);
            a3 = fmaf(v.w, w[4 * k + 3], a3);
        }
        float acc = (a0 + a1) + (a2 + a3);
        g_h1[n * 128 + j] = acc;
        float ps = acc * asj;
        float pd = acc * adj;
#pragma unroll
        for (int off = 16; off > 0; off >>= 1) {
            ps += __shfl_down_sync(0xffffffffu, ps, off);
            pd += __shfl_down_sync(0xffffffffu, pd, off);
        }
        if (lane == 0) {
            g_asrc1[n * 4 + head] = ps;
            g_adst1[n * 4 + head] = pd;
        }
    }
}

// ---------------- fused layer 1: softmax + aggregate + ELU + W2 proj ----------------
// one warp per destination node; per-chunk (src, exp) staged through smem
__global__ __launch_bounds__(256) void k_layer1(const float* __restrict__ b1,
                                                const float* __restrict__ W2,
                                                const float* __restrict__ att_s2,
                                                const float* __restrict__ att_d2) {
    __shared__ int   ssrc[256];
    __shared__ float sex[256 * 4];
    int gt = blockIdx.x * blockDim.x + threadIdx.x;
    int n = gt >> 5;
    if (n >= NN) return;
    const int lane = gt & 31;
    const int head = lane >> 3;
    const int wslot = (threadIdx.x >> 5) * 32;    // this warp's smem base
    const unsigned FULL = 0xffffffffu;

    const int beg = g_rowstart[n];
    const int deg = g_deg[n];
    const int end = beg + deg;
    const float4 adn = reinterpret_cast<const float4*>(g_adst1)[n];
    const float4* __restrict__ h1v = reinterpret_cast<const float4*>(g_h1);

    float acc0 = 0.0f, acc1 = 0.0f, acc2 = 0.0f, acc3 = 0.0f;
    float dx = 0.0f, dy = 0.0f, dz = 0.0f, dw = 0.0f;

    for (int c = beg; c < end; c += 32) {
        const int idx = c + lane;
        const int cnt = min(32, end - c);
        __syncwarp(FULL);
        if (idx < end) {
            int s = g_csrc[idx];
            float4 as_ = reinterpret_cast<const float4*>(g_asrc1)[s];
            float v0 = as_.x + adn.x, v1 = as_.y + adn.y;
            float v2 = as_.z + adn.z, v3 = as_.w + adn.w;
            v0 = (v0 > 0.0f) ? v0 : NEG_SLOPE * v0;
            v1 = (v1 > 0.0f) ? v1 : NEG_SLOPE * v1;
            v2 = (v2 > 0.0f) ? v2 : NEG_SLOPE * v2;
            v3 = (v3 > 0.0f) ? v3 : NEG_SLOPE * v3;
            float e0 = expf(v0), e1 = expf(v1), e2 = expf(v2), e3 = expf(v3);
            dx += e0; dy += e1; dz += e2; dw += e3;
            ssrc[wslot + lane] = s;
            float* p = &sex[(wslot + lane) * 4];
            p[0] = e0; p[1] = e1; p[2] = e2; p[3] = e3;
        }
        __syncwarp(FULL);
        // gather phase: 2-deep software pipeline for MLP
        int j = 0;
        for (; j + 1 < cnt; j += 2) {
            int sA = ssrc[wslot + j];
            int sB = ssrc[wslot + j + 1];
            float4 hA = h1v[sA * 32 + lane];
            float4 hB = h1v[sB * 32 + lane];
            float exA = sex[(wslot + j) * 4 + head];
            float exB = sex[(wslot + j + 1) * 4 + head];
            acc0 = fmaf(exA, hA.x, acc0);
            acc1 = fmaf(exA, hA.y, acc1);
            acc2 = fmaf(exA, hA.z, acc2);
            acc3 = fmaf(exA, hA.w, acc3);
            acc0 = fmaf(exB, hB.x, acc0);
            acc1 = fmaf(exB, hB.y, acc1);
            acc2 = fmaf(exB, hB.z, acc2);
            acc3 = fmaf(exB, hB.w, acc3);
        }
        if (j < cnt) {
            int sA = ssrc[wslot + j];
            float4 hA = h1v[sA * 32 + lane];
            float exA = sex[(wslot + j) * 4 + head];
            acc0 = fmaf(exA, hA.x, acc0);
            acc1 = fmaf(exA, hA.y, acc1);
            acc2 = fmaf(exA, hA.z, acc2);
            acc3 = fmaf(exA, hA.w, acc3);
        }
    }
    // full-warp reduce of the 4 denominators (result in all lanes)
#pragma unroll
    for (int off = 16; off > 0; off >>= 1) {
        dx += __shfl_xor_sync(FULL, dx, off);
        dy += __shfl_xor_sync(FULL, dy, off);
        dz += __shfl_xor_sync(FULL, dz, off);
        dw += __shfl_xor_sync(FULL, dw, off);
    }
    float denh = (head == 0) ? dx : (head == 1) ? dy : (head == 2) ? dz : dw;
    float r = 1.0f / (denh + EPS_DEN);

    // epilogue: normalize, +b1, ELU, project with W2
    float p0 = 0.0f, p1 = 0.0f;
    float av[4] = {acc0, acc1, acc2, acc3};
#pragma unroll
    for (int m = 0; m < 4; m++) {
        int k = 4 * lane + m;
        float v = av[m] * r + b1[k];
        float ev = (v > 0.0f) ? v : expm1f(v);   // ELU
        p0 = fmaf(ev, W2[k * 2 + 0], p0);
        p1 = fmaf(ev, W2[k * 2 + 1], p1);
    }
#pragma unroll
    for (int off = 16; off > 0; off >>= 1) {
        p0 += __shfl_down_sync(FULL, p0, off);
        p1 += __shfl_down_sync(FULL, p1, off);
    }
    if (lane == 0) {
        g_h2[n * 2 + 0] = p0;
        g_h2[n * 2 + 1] = p1;
        g_asrc2[n] = p0 * att_s2[0] + p1 * att_s2[1];
        g_adst2[n] = p0 * att_d2[0] + p1 * att_d2[1];
    }
}

// ---------------- fused layer 2: softmax + aggregate + log_softmax ----------------
// 8 lanes per destination node (avg degree ~17)
__global__ __launch_bounds__(256) void k_layer2(const float* __restrict__ b2,
                                                float* __restrict__ out) {
    int gt = blockIdx.x * blockDim.x + threadIdx.x;
    int n = gt >> 3;
    if (n >= NN) return;
    const int lane = gt & 7;
    const unsigned FULL = 0xffffffffu;

    const int beg = g_rowstart[n];
    const int end = beg + g_deg[n];
    const float adn = g_adst2[n];

    float den = 0.0f, o0 = 0.0f, o1 = 0.0f;
    for (int idx = beg + lane; idx < end; idx += 8) {
        int s = g_csrc[idx];
        float v = g_asrc2[s] + adn;
        v = (v > 0.0f) ? v : NEG_SLOPE * v;
        float ex = expf(v);
        float2 h = reinterpret_cast<const float2*>(g_h2)[s];
        den += ex;
        o0 = fmaf(ex, h.x, o0);
        o1 = fmaf(ex, h.y, o1);
    }
#pragma unroll
    for (int off = 4; off > 0; off >>= 1) {
        den += __shfl_down_sync(FULL, den, off, 8);
        o0  += __shfl_down_sync(FULL, o0, off, 8);
        o1  += __shfl_down_sync(FULL, o1, off, 8);
    }
    if (lane == 0) {
        float r = 1.0f / (den + EPS_DEN);
        float a = o0 * r + b2[0];
        float b = o1 * r + b2[1];
        float m = fmaxf(a, b);
        float l = m + logf(expf(a - m) + expf(b - m));
        out[n * 2 + 0] = a - l;
        out[n * 2 + 1] = b - l;
    }
}

// ---------------- launch ----------------
extern "C" void kernel_launch(void* const* d_in, const int* in_sizes, int n_in,
                              void* d_out, int out_size) {
    const float* x    = (const float*)d_in[0];
    const int*   ei   = (const int*)d_in[1];
    const float* W1   = (const float*)d_in[2];
    const float* as1  = (const float*)d_in[3];
    const float* ad1  = (const float*)d_in[4];
    const float* b1   = (const float*)d_in[5];
    const float* W2   = (const float*)d_in[6];
    const float* as2  = (const float*)d_in[7];
    const float* ad2  = (const float*)d_in[8];
    const float* b2   = (const float*)d_in[9];
    float* out = (float*)d_out;

    (void)in_sizes; (void)n_in; (void)out_size;

    // one-time side stream + events for capture-legal fork/join (created outside
    // capture on the correctness call; reused by the capture call — identical
    // work is enqueued on every call)
    static cudaStream_t s_side = nullptr;
    static cudaEvent_t  s_evFork = nullptr, s_evJoin = nullptr;
    if (s_side == nullptr) {
        cudaStreamCreateWithFlags(&s_side, cudaStreamNonBlocking);
        cudaEventCreateWithFlags(&s_evFork, cudaEventDisableTiming);
        cudaEventCreateWithFlags(&s_evJoin, cudaEventDisableTiming);
    }

    // fork: CSR build on side stream, gemm1 on main stream (disjoint state)
    cudaEventRecord(s_evFork, 0);
    cudaStreamWaitEvent(s_side, s_evFork, 0);

    k_initdeg<<<(NN + 255) / 256, 256, 0, s_side>>>();
    k_count<<<(EE + 255) / 256, 256, 0, s_side>>>(ei);
    k_offsets<<<(NN + 255) / 256, 256, 0, s_side>>>();
    k_scatter<<<(ETOT + 255) / 256, 256, 0, s_side>>>(ei);
    cudaEventRecord(s_evJoin, s_side);

    k_gemm1<<<(NN + GEMM1_NPB - 1) / GEMM1_NPB, 128>>>(x, W1, as1, ad1);

    // join: layer kernels need both CSR and gemm outputs
    cudaStreamWaitEvent(0, s_evJoin, 0);

    {
        long long tot = (long long)NN * 32;
        k_layer1<<<(int)((tot + 255) / 256), 256>>>(b1, W2, as2, ad2);
    }
    {
        long long tot = (long long)NN * 8;
        k_layer2<<<(int)((tot + 255) / 256), 256>>>(b2, out);
    }
}